// round 3
// baseline (speedup 1.0000x reference)
#include <cuda_runtime.h>
#include <math.h>

#define NN 100000
#define DD 256
#define ND4 (DD / 4)
#define EE 3200000

// Scratch (static device globals — 16B-aligned via float4)
__device__ float  g_dis[NN];                        // degree, then rsqrt(degree)
__device__ float4 g_y  [(size_t)NN * ND4];          // (x@W) * dis[row]
__device__ float4 g_acc[(size_t)NN * ND4];          // scatter accumulator
__device__ float4 g_h  [(size_t)NN * ND4];          // layer-1 output
__device__ int    g_src[EE];
__device__ int    g_dst[EE];
__device__ int    g_is32;                           // 1 if edge_index is int32

// ---------------- dtype probe + index conversion ----------------

__global__ void k_probe(const int* __restrict__ ei_raw) {
    // If data is int64 (little-endian, values in [0, 1e5)), every odd word is 0.
    // If int32, odd words are random node ids — almost surely nonzero.
    __shared__ int any;
    if (threadIdx.x == 0) any = 0;
    __syncthreads();
    if (ei_raw[threadIdx.x * 2 + 1] != 0) atomicOr(&any, 1);
    __syncthreads();
    if (threadIdx.x == 0) g_is32 = any;
}

__global__ void k_convert(const void* __restrict__ ei_raw, int e) {
    int i = blockIdx.x * blockDim.x + threadIdx.x;
    if (i >= e) return;
    if (g_is32) {
        const int* p = (const int*)ei_raw;
        g_src[i] = p[i];
        g_dst[i] = p[e + i];
    } else {
        const long long* p = (const long long*)ei_raw;
        g_src[i] = (int)p[i];
        g_dst[i] = (int)p[e + i];
    }
}

// ---------------- degree / norm ----------------

__global__ void k_deg_init(int n) {
    int i = blockIdx.x * blockDim.x + threadIdx.x;
    if (i < n) g_dis[i] = 1.0f;   // self loop
}

__global__ void k_deg_accum(int e) {
    int i = blockIdx.x * blockDim.x + threadIdx.x;
    if (i < e) atomicAdd(&g_dis[g_dst[i]], 1.0f);
}

__global__ void k_rsqrt(int n) {
    int i = blockIdx.x * blockDim.x + threadIdx.x;
    if (i < n) g_dis[i] = rsqrtf(g_dis[i]);
}

// ---------------- GEMM: Y = (A @ W) * dis[row]; Acc = Y (self-loop init) ----------------
// BM=64, BN=64, BK=32, 256 threads, 4x4 microtile per thread.

__global__ void k_gemm_scale(const float* __restrict__ A, const float* __restrict__ W,
                             int n) {
    __shared__ float As[32][65];   // [k][m], padded
    __shared__ float Ws[32][64];   // [k][n]

    const int tid = threadIdx.x;
    const int tx = tid & 15;
    const int ty = tid >> 4;
    const int rowBase = blockIdx.y * 64;
    const int colBase = blockIdx.x * 64;

    float acc[4][4] = {};

    for (int kb = 0; kb < DD; kb += 32) {
#pragma unroll
        for (int i = 0; i < 2; i++) {
            int f  = tid * 2 + i;
            int r  = f >> 3;
            int k4 = (f & 7) * 4;
            int grow = rowBase + r;
            float4 v = make_float4(0.f, 0.f, 0.f, 0.f);
            if (grow < n)
                v = *(const float4*)(A + (size_t)grow * DD + kb + k4);
            As[k4 + 0][r] = v.x;
            As[k4 + 1][r] = v.y;
            As[k4 + 2][r] = v.z;
            As[k4 + 3][r] = v.w;
        }
#pragma unroll
        for (int i = 0; i < 2; i++) {
            int f  = tid * 2 + i;
            int r  = f >> 4;
            int c4 = (f & 15) * 4;
            *(float4*)(&Ws[r][c4]) =
                *(const float4*)(W + (size_t)(kb + r) * DD + colBase + c4);
        }
        __syncthreads();

#pragma unroll
        for (int k = 0; k < 32; k++) {
            float a0 = As[k][ty * 4 + 0];
            float a1 = As[k][ty * 4 + 1];
            float a2 = As[k][ty * 4 + 2];
            float a3 = As[k][ty * 4 + 3];
            float4 b = *(float4*)(&Ws[k][tx * 4]);
            acc[0][0] += a0 * b.x; acc[0][1] += a0 * b.y; acc[0][2] += a0 * b.z; acc[0][3] += a0 * b.w;
            acc[1][0] += a1 * b.x; acc[1][1] += a1 * b.y; acc[1][2] += a1 * b.z; acc[1][3] += a1 * b.w;
            acc[2][0] += a2 * b.x; acc[2][1] += a2 * b.y; acc[2][2] += a2 * b.z; acc[2][3] += a2 * b.w;
            acc[3][0] += a3 * b.x; acc[3][1] += a3 * b.y; acc[3][2] += a3 * b.z; acc[3][3] += a3 * b.w;
        }
        __syncthreads();
    }

#pragma unroll
    for (int m = 0; m < 4; m++) {
        int grow = rowBase + ty * 4 + m;
        if (grow < n) {
            float s = g_dis[grow];
            float4 o = make_float4(acc[m][0] * s, acc[m][1] * s,
                                   acc[m][2] * s, acc[m][3] * s);
            size_t off = (size_t)grow * ND4 + colBase / 4 + tx;
            g_y[off]   = o;
            g_acc[off] = o;   // self-loop contribution
        }
    }
}

// ---------------- scatter: acc[dst] += y[src]  (one warp per edge) ----------------

__global__ void k_scatter(int e) {
    int w    = (int)((blockIdx.x * (size_t)blockDim.x + threadIdx.x) >> 5);
    int lane = threadIdx.x & 31;
    if (w >= e) return;
    int s = g_src[w];
    int d = g_dst[w];
    const float4* ys = g_y   + (size_t)s * ND4;
    float4*       ad = g_acc + (size_t)d * ND4;
    float4 v0 = ys[lane];
    float4 v1 = ys[lane + 32];
    asm volatile("red.global.add.v4.f32 [%0], {%1,%2,%3,%4};"
                 :: "l"(ad + lane), "f"(v0.x), "f"(v0.y), "f"(v0.z), "f"(v0.w)
                 : "memory");
    asm volatile("red.global.add.v4.f32 [%0], {%1,%2,%3,%4};"
                 :: "l"(ad + lane + 32), "f"(v1.x), "f"(v1.y), "f"(v1.z), "f"(v1.w)
                 : "memory");
}

// ---------------- finalize: H = elu(dis[row]*acc + b) ----------------

__device__ __forceinline__ float elu1(float x) {
    return x > 0.f ? x : (expf(x) - 1.0f);
}

__global__ void k_finalize(const float* __restrict__ b, float4* __restrict__ H, int n) {
    size_t i = blockIdx.x * (size_t)blockDim.x + threadIdx.x;
    size_t total = (size_t)n * ND4;
    if (i >= total) return;
    int row = (int)(i / ND4);
    int c4  = (int)(i % ND4) * 4;
    float s = g_dis[row];
    float4 a  = g_acc[i];
    float4 bb = *(const float4*)(b + c4);
    float4 o;
    o.x = elu1(fmaf(a.x, s, bb.x));
    o.y = elu1(fmaf(a.y, s, bb.y));
    o.z = elu1(fmaf(a.z, s, bb.z));
    o.w = elu1(fmaf(a.w, s, bb.w));
    H[i] = o;
}

// ---------------- launch ----------------

extern "C" void kernel_launch(void* const* d_in, const int* in_sizes, int n_in,
                              void* d_out, int out_size) {
    const float* x  = (const float*)d_in[0];
    const void*  ei = d_in[1];                 // [2, E], int32 or int64 — probed
    const float* W1 = (const float*)d_in[2];
    const float* b1 = (const float*)d_in[3];
    const float* W2 = (const float*)d_in[4];
    const float* b2 = (const float*)d_in[5];
    float4* out = (float4*)d_out;

    int n = in_sizes[0] / DD;        // 100000
    int e = in_sizes[1] / 2;         // 3200000

    void* p_h = nullptr;
    cudaGetSymbolAddress(&p_h, g_h);
    float4* hbuf = (float4*)p_h;

    // probe dtype + convert indices
    k_probe  <<<1, 512>>>((const int*)ei);
    k_convert<<<(e + 255) / 256, 256>>>(ei, e);

    // norms
    k_deg_init <<<(n + 255) / 256, 256>>>(n);
    k_deg_accum<<<(e + 255) / 256, 256>>>(e);
    k_rsqrt    <<<(n + 255) / 256, 256>>>(n);

    dim3 gGrid(DD / 64, (n + 63) / 64);
    size_t nf4 = (size_t)n * ND4;
    int fGrid = (int)((nf4 + 255) / 256);
    int sGrid = (e + 7) / 8;                 // 8 warps (edges) per block

    // layer 1: x -> g_h
    k_gemm_scale<<<gGrid, 256>>>(x, W1, n);
    k_scatter   <<<sGrid, 256>>>(e);
    k_finalize  <<<fGrid, 256>>>(b1, hbuf, n);

    // layer 2: g_h -> out
    k_gemm_scale<<<gGrid, 256>>>((const float*)hbuf, W2, n);
    k_scatter   <<<sGrid, 256>>>(e);
    k_finalize  <<<fGrid, 256>>>(b2, out, n);
}

// round 4
// speedup vs baseline: 1.8991x; 1.8991x over previous
#include <cuda_runtime.h>
#include <math.h>

#define NN 100000
#define DD 256
#define ND4 (DD / 4)
#define EE 3200000

// Scratch (static device globals)
__device__ float  g_dis[NN];                        // rsqrt(1 + indeg)
__device__ int    g_deg[NN];
__device__ int    g_rowptr[NN + 1];
__device__ int    g_cursor[NN];
__device__ int    g_nbr[EE];                        // CSR: src ids grouped by dst
__device__ float4 g_y  [(size_t)NN * ND4];          // (x@W) * dis[row]
__device__ float4 g_h  [(size_t)NN * ND4];          // layer-1 output
__device__ int    g_src[EE];
__device__ int    g_dst[EE];
__device__ int    g_is32;

// ---------------- dtype probe + index conversion ----------------

__global__ void k_probe(const int* __restrict__ ei_raw) {
    // int64 node ids < 1e5 -> every odd 32-bit word is 0. int32 -> random ids.
    __shared__ int any;
    if (threadIdx.x == 0) any = 0;
    __syncthreads();
    if (ei_raw[threadIdx.x * 2 + 1] != 0) atomicOr(&any, 1);
    __syncthreads();
    if (threadIdx.x == 0) g_is32 = any;
}

__global__ void k_convert(const void* __restrict__ ei_raw, int e) {
    int i = blockIdx.x * blockDim.x + threadIdx.x;
    if (i >= e) return;
    if (g_is32) {
        const int* p = (const int*)ei_raw;
        g_src[i] = p[i];
        g_dst[i] = p[e + i];
    } else {
        const long long* p = (const long long*)ei_raw;
        g_src[i] = (int)p[i];
        g_dst[i] = (int)p[e + i];
    }
}

// ---------------- degree / CSR build ----------------

__global__ void k_deg_zero(int n) {
    int i = blockIdx.x * blockDim.x + threadIdx.x;
    if (i < n) g_deg[i] = 0;
}

__global__ void k_deg_accum(int e) {
    int i = blockIdx.x * blockDim.x + threadIdx.x;
    if (i < e) atomicAdd(&g_deg[g_dst[i]], 1);
}

// Single-block exclusive prefix scan over g_deg -> g_rowptr / g_cursor.
__global__ void k_scan(int n) {
    __shared__ int sums[1024];
    const int t = threadIdx.x;
    const int chunk = (n + 1023) / 1024;          // 98
    const int lo = t * chunk;
    const int hi = min(lo + chunk, n);

    int s = 0;
    for (int i = lo; i < hi; i++) s += g_deg[i];
    sums[t] = s;
    __syncthreads();

    // Hillis-Steele inclusive scan over 1024 partials
    for (int off = 1; off < 1024; off <<= 1) {
        int v = (t >= off) ? sums[t - off] : 0;
        __syncthreads();
        sums[t] += v;
        __syncthreads();
    }

    int run = (t > 0) ? sums[t - 1] : 0;          // exclusive offset
    for (int i = lo; i < hi; i++) {
        g_rowptr[i] = run;
        g_cursor[i] = run;
        run += g_deg[i];
    }
    if (t == 1023) g_rowptr[n] = sums[1023];
}

__global__ void k_dis(int n) {
    int i = blockIdx.x * blockDim.x + threadIdx.x;
    if (i < n) g_dis[i] = rsqrtf((float)(g_deg[i] + 1));
}

__global__ void k_fill(int e) {
    int i = blockIdx.x * blockDim.x + threadIdx.x;
    if (i >= e) return;
    int pos = atomicAdd(&g_cursor[g_dst[i]], 1);
    g_nbr[pos] = g_src[i];
}

// ---------------- GEMM: Y = (A @ W) * dis[row] ----------------
// 128x128 block tile, BK=8, 256 threads, 8x8 microtile, double-buffered smem.

__global__ void __launch_bounds__(256, 2)
k_gemm_scale(const float* __restrict__ A, const float* __restrict__ W, int n) {
    __shared__ float As[2][8][128];
    __shared__ float Bs[2][8][128];

    const int tid = threadIdx.x;
    const int tx = tid & 15;            // 0..15 -> 8 cols each
    const int ty = tid >> 4;            // 0..15 -> 8 rows each
    const int rowBase = blockIdx.y * 128;
    const int colBase = blockIdx.x * 128;

    // A staging: thread -> (row, k0)
    const int arow = tid >> 1;          // 0..127
    const int ak0  = (tid & 1) * 4;     // 0 or 4
    // B staging: thread -> (k, col4)
    const int bk   = tid >> 5;          // 0..7
    const int bc4  = (tid & 31) * 4;    // 0..124

    float acc[8][8] = {};
    float4 aReg, bReg;

    // prologue: load k-block 0 into buffer 0
    {
        int grow = rowBase + arow;
        aReg = make_float4(0.f, 0.f, 0.f, 0.f);
        if (grow < n) aReg = *(const float4*)(A + (size_t)grow * DD + ak0);
        bReg = *(const float4*)(W + (size_t)bk * DD + colBase + bc4);
        As[0][ak0 + 0][arow] = aReg.x;
        As[0][ak0 + 1][arow] = aReg.y;
        As[0][ak0 + 2][arow] = aReg.z;
        As[0][ak0 + 3][arow] = aReg.w;
        *(float4*)(&Bs[0][bk][bc4]) = bReg;
    }
    __syncthreads();

    int buf = 0;
    const int NKB = DD / 8;             // 32
    for (int kb = 0; kb < NKB; kb++) {
        if (kb + 1 < NKB) {
            int kbase = (kb + 1) * 8;
            int grow = rowBase + arow;
            aReg = make_float4(0.f, 0.f, 0.f, 0.f);
            if (grow < n) aReg = *(const float4*)(A + (size_t)grow * DD + kbase + ak0);
            bReg = *(const float4*)(W + (size_t)(kbase + bk) * DD + colBase + bc4);
        }

#pragma unroll
        for (int k = 0; k < 8; k++) {
            float a[8], b[8];
            *(float4*)&a[0] = *(float4*)(&As[buf][k][ty * 8]);
            *(float4*)&a[4] = *(float4*)(&As[buf][k][ty * 8 + 4]);
            *(float4*)&b[0] = *(float4*)(&Bs[buf][k][tx * 8]);
            *(float4*)&b[4] = *(float4*)(&Bs[buf][k][tx * 8 + 4]);
#pragma unroll
            for (int m = 0; m < 8; m++)
#pragma unroll
                for (int c = 0; c < 8; c++)
                    acc[m][c] += a[m] * b[c];
        }

        if (kb + 1 < NKB) {
            int nb = buf ^ 1;
            As[nb][ak0 + 0][arow] = aReg.x;
            As[nb][ak0 + 1][arow] = aReg.y;
            As[nb][ak0 + 2][arow] = aReg.z;
            As[nb][ak0 + 3][arow] = aReg.w;
            *(float4*)(&Bs[nb][bk][bc4]) = bReg;
            __syncthreads();
            buf = nb;
        }
    }

#pragma unroll
    for (int m = 0; m < 8; m++) {
        int grow = rowBase + ty * 8 + m;
        if (grow < n) {
            float s = g_dis[grow];
            float4 o0 = make_float4(acc[m][0] * s, acc[m][1] * s,
                                    acc[m][2] * s, acc[m][3] * s);
            float4 o1 = make_float4(acc[m][4] * s, acc[m][5] * s,
                                    acc[m][6] * s, acc[m][7] * s);
            size_t off = (size_t)grow * ND4 + (colBase >> 2) + tx * 2;
            g_y[off]     = o0;
            g_y[off + 1] = o1;
        }
    }
}

// ---------------- pull + epilogue: H[v] = elu(dis[v]*(y[v] + sum_nbr y[s]) + b) ----

__device__ __forceinline__ float elu1(float x) {
    return x > 0.f ? x : (expf(x) - 1.0f);
}

__global__ void __launch_bounds__(256)
k_pull(const float4* __restrict__ b, float4* __restrict__ H, int n) {
    const int warp = (blockIdx.x * blockDim.x + threadIdx.x) >> 5;
    const int lane = threadIdx.x & 31;
    if (warp >= n) return;
    const int node = warp;

    const float4* yrow = g_y + (size_t)node * ND4;
    float4 acc0 = yrow[lane];            // self loop
    float4 acc1 = yrow[lane + 32];

    int j   = g_rowptr[node];
    int end = g_rowptr[node + 1];

    for (; j + 1 < end; j += 2) {
        int s0 = g_nbr[j];
        int s1 = g_nbr[j + 1];
        const float4* p0 = g_y + (size_t)s0 * ND4;
        const float4* p1 = g_y + (size_t)s1 * ND4;
        float4 u0 = p0[lane];
        float4 u1 = p0[lane + 32];
        float4 v0 = p1[lane];
        float4 v1 = p1[lane + 32];
        acc0.x += u0.x; acc0.y += u0.y; acc0.z += u0.z; acc0.w += u0.w;
        acc1.x += u1.x; acc1.y += u1.y; acc1.z += u1.z; acc1.w += u1.w;
        acc0.x += v0.x; acc0.y += v0.y; acc0.z += v0.z; acc0.w += v0.w;
        acc1.x += v1.x; acc1.y += v1.y; acc1.z += v1.z; acc1.w += v1.w;
    }
    if (j < end) {
        int s0 = g_nbr[j];
        const float4* p0 = g_y + (size_t)s0 * ND4;
        float4 u0 = p0[lane];
        float4 u1 = p0[lane + 32];
        acc0.x += u0.x; acc0.y += u0.y; acc0.z += u0.z; acc0.w += u0.w;
        acc1.x += u1.x; acc1.y += u1.y; acc1.z += u1.z; acc1.w += u1.w;
    }

    float s = g_dis[node];
    float4 b0 = b[lane];
    float4 b1 = b[lane + 32];
    float4 o0, o1;
    o0.x = elu1(fmaf(acc0.x, s, b0.x));
    o0.y = elu1(fmaf(acc0.y, s, b0.y));
    o0.z = elu1(fmaf(acc0.z, s, b0.z));
    o0.w = elu1(fmaf(acc0.w, s, b0.w));
    o1.x = elu1(fmaf(acc1.x, s, b1.x));
    o1.y = elu1(fmaf(acc1.y, s, b1.y));
    o1.z = elu1(fmaf(acc1.z, s, b1.z));
    o1.w = elu1(fmaf(acc1.w, s, b1.w));
    H[(size_t)node * ND4 + lane]      = o0;
    H[(size_t)node * ND4 + lane + 32] = o1;
}

// ---------------- launch ----------------

extern "C" void kernel_launch(void* const* d_in, const int* in_sizes, int n_in,
                              void* d_out, int out_size) {
    const float* x  = (const float*)d_in[0];
    const void*  ei = d_in[1];
    const float* W1 = (const float*)d_in[2];
    const float* b1 = (const float*)d_in[3];
    const float* W2 = (const float*)d_in[4];
    const float* b2 = (const float*)d_in[5];
    float4* out = (float4*)d_out;

    int n = in_sizes[0] / DD;        // 100000
    int e = in_sizes[1] / 2;         // 3200000

    void* p_h = nullptr;
    cudaGetSymbolAddress(&p_h, g_h);
    float4* hbuf = (float4*)p_h;

    // indices + CSR build
    k_probe    <<<1, 512>>>((const int*)ei);
    k_convert  <<<(e + 255) / 256, 256>>>(ei, e);
    k_deg_zero <<<(n + 255) / 256, 256>>>(n);
    k_deg_accum<<<(e + 255) / 256, 256>>>(e);
    k_scan     <<<1, 1024>>>(n);
    k_dis      <<<(n + 255) / 256, 256>>>(n);
    k_fill     <<<(e + 255) / 256, 256>>>(e);

    dim3 gGrid(DD / 128, (n + 127) / 128);
    int pGrid = (n + 7) / 8;                     // 8 warps (nodes) per block

    // layer 1: x -> g_h
    k_gemm_scale<<<gGrid, 256>>>(x, W1, n);
    k_pull      <<<pGrid, 256>>>((const float4*)b1, hbuf, n);

    // layer 2: g_h -> out
    k_gemm_scale<<<gGrid, 256>>>((const float*)hbuf, W2, n);
    k_pull      <<<pGrid, 256>>>((const float4*)b2, out, n);
}

// round 5
// speedup vs baseline: 2.2679x; 1.1942x over previous
#include <cuda_runtime.h>
#include <math.h>

#define NN 100000
#define DD 256
#define ND4 (DD / 4)
#define EE 3200000

// Scratch (static device globals)
__device__ float  g_dis[NN];
__device__ int    g_deg[NN];
__device__ int    g_rowptr[NN + 1];
__device__ int    g_cursor[NN];
__device__ int    g_nbr[EE];
__device__ float4 g_y[(size_t)NN * ND4];
__device__ float4 g_h[(size_t)NN * ND4];
__device__ int    g_is32;

// ---------------- dtype probe ----------------

__global__ void k_probe(const int* __restrict__ ei_raw) {
    __shared__ int any;
    if (threadIdx.x == 0) any = 0;
    __syncthreads();
    if (ei_raw[threadIdx.x * 2 + 1] != 0) atomicOr(&any, 1);
    __syncthreads();
    if (threadIdx.x == 0) g_is32 = any;
}

__device__ __forceinline__ int edge_id(const void* p, size_t idx) {
    return g_is32 ? ((const int*)p)[idx] : (int)((const long long*)p)[idx];
}

// ---------------- degree / CSR build ----------------

__global__ void k_deg_zero(int n) {
    int i = blockIdx.x * blockDim.x + threadIdx.x;
    if (i < n) g_deg[i] = 0;
}

__global__ void k_deg_accum(const void* __restrict__ ei, int e) {
    int i = blockIdx.x * blockDim.x + threadIdx.x;
    if (i < e) atomicAdd(&g_deg[edge_id(ei, (size_t)e + i)], 1);
}

__global__ void k_scan(int n) {
    __shared__ int sums[1024];
    const int t = threadIdx.x;
    const int chunk = (n + 1023) / 1024;
    const int lo = t * chunk;
    const int hi = min(lo + chunk, n);

    int s = 0;
    for (int i = lo; i < hi; i++) s += g_deg[i];
    sums[t] = s;
    __syncthreads();
    for (int off = 1; off < 1024; off <<= 1) {
        int v = (t >= off) ? sums[t - off] : 0;
        __syncthreads();
        sums[t] += v;
        __syncthreads();
    }
    int run = (t > 0) ? sums[t - 1] : 0;
    for (int i = lo; i < hi; i++) {
        g_rowptr[i] = run;
        g_cursor[i] = run;
        run += g_deg[i];
    }
    if (t == 1023) g_rowptr[n] = sums[1023];
}

__global__ void k_dis(int n) {
    int i = blockIdx.x * blockDim.x + threadIdx.x;
    if (i < n) g_dis[i] = rsqrtf((float)(g_deg[i] + 1));
}

__global__ void k_fill(const void* __restrict__ ei, int e) {
    int i = blockIdx.x * blockDim.x + threadIdx.x;
    if (i >= e) return;
    int s = edge_id(ei, i);
    int d = edge_id(ei, (size_t)e + i);
    int pos = atomicAdd(&g_cursor[d], 1);
    g_nbr[pos] = s;
}

// ---------------- tf32 helpers ----------------

__device__ __forceinline__ unsigned f2tf(float x) {
    unsigned r;
    asm("cvt.rna.tf32.f32 %0, %1;" : "=r"(r) : "f"(x));
    return r;
}

__device__ __forceinline__ void mma8(float acc[4], const unsigned a[4], const unsigned b[2]) {
    asm volatile(
        "mma.sync.aligned.m16n8k8.row.col.f32.tf32.tf32.f32 "
        "{%0,%1,%2,%3},{%4,%5,%6,%7},{%8,%9},{%0,%1,%2,%3};"
        : "+f"(acc[0]), "+f"(acc[1]), "+f"(acc[2]), "+f"(acc[3])
        : "r"(a[0]), "r"(a[1]), "r"(a[2]), "r"(a[3]), "r"(b[0]), "r"(b[1]));
}

// ---------------- GEMM: Y = (A @ W) * dis[row]  (tensor core, tf32 3-term split) ----
// Block 128x128, kc=16, 8 warps, warptile 64x32 (4 m16-tiles x 4 n8-tiles).

#define APAD 20     // A smem row stride (floats), conflict-free frag loads
#define BPAD 136    // B smem row stride (floats)
#define ABUF (128 * APAD)
#define BBUF (16 * BPAD)
#define SM_FLOATS (2 * ABUF * 2 + 2 * BBUF * 2)

__global__ void __launch_bounds__(256)
k_gemm_tc(const float* __restrict__ A, const float* __restrict__ W, int n) {
    extern __shared__ float sm[];
    float* sAh = sm;
    float* sAl = sAh + 2 * ABUF;
    float* sBh = sAl + 2 * ABUF;
    float* sBl = sBh + 2 * BBUF;

    const int tid  = threadIdx.x;
    const int lane = tid & 31;
    const int warp = tid >> 5;
    const int wm = (warp & 1) * 64;
    const int wn = (warp >> 1) * 32;
    const int qr = lane >> 2;
    const int qc = lane & 3;
    const int rowBase = blockIdx.y * 128;
    const int colBase = blockIdx.x * 128;

    // staging coords
    const int ar  = tid >> 2;         // A rows: ar, ar+64
    const int ak4 = (tid & 3) * 4;
    const int bkr = tid >> 5;         // B k-rows: bkr, bkr+8
    const int bc4 = (tid & 31) * 4;

    float acc[4][4][4] = {};
    float4 aR[2], bR[2];

#define LOAD_G(kbase)                                                              \
    {                                                                              \
        _Pragma("unroll")                                                          \
        for (int i = 0; i < 2; i++) {                                              \
            int grow = rowBase + ar + i * 64;                                      \
            aR[i] = make_float4(0.f, 0.f, 0.f, 0.f);                               \
            if (grow < n)                                                          \
                aR[i] = *(const float4*)(A + (size_t)grow * DD + (kbase) + ak4);   \
            bR[i] = *(const float4*)(W + (size_t)((kbase) + bkr + i * 8) * DD      \
                                        + colBase + bc4);                          \
        }                                                                          \
    }

#define STORE_S(buf)                                                               \
    {                                                                              \
        _Pragma("unroll")                                                          \
        for (int i = 0; i < 2; i++) {                                              \
            int abase = (buf) * ABUF + (ar + i * 64) * APAD + ak4;                 \
            const float* av = (const float*)&aR[i];                                \
            _Pragma("unroll")                                                      \
            for (int j = 0; j < 4; j++) {                                          \
                unsigned h = f2tf(av[j]);                                          \
                float hf = __uint_as_float(h);                                     \
                sAh[abase + j] = hf;                                               \
                sAl[abase + j] = __uint_as_float(f2tf(av[j] - hf));                \
            }                                                                      \
            int bbase = (buf) * BBUF + (bkr + i * 8) * BPAD + bc4;                 \
            const float* bv = (const float*)&bR[i];                                \
            _Pragma("unroll")                                                      \
            for (int j = 0; j < 4; j++) {                                          \
                unsigned h = f2tf(bv[j]);                                          \
                float hf = __uint_as_float(h);                                     \
                sBh[bbase + j] = hf;                                               \
                sBl[bbase + j] = __uint_as_float(f2tf(bv[j] - hf));                \
            }                                                                      \
        }                                                                          \
    }

    LOAD_G(0)
    STORE_S(0)
    __syncthreads();

    const int NSTAGE = DD / 16;                  // 16
    for (int s = 0; s < NSTAGE; s++) {
        int buf = s & 1;
        if (s + 1 < NSTAGE) LOAD_G((s + 1) * 16)

#pragma unroll
        for (int kk = 0; kk < 16; kk += 8) {
            unsigned bh[4][2], bl[4][2];
#pragma unroll
            for (int nt = 0; nt < 4; nt++) {
                int nn = wn + nt * 8 + qr;
                int b0 = buf * BBUF + (kk + qc) * BPAD + nn;
                int b1 = buf * BBUF + (kk + qc + 4) * BPAD + nn;
                bh[nt][0] = __float_as_uint(sBh[b0]);
                bh[nt][1] = __float_as_uint(sBh[b1]);
                bl[nt][0] = __float_as_uint(sBl[b0]);
                bl[nt][1] = __float_as_uint(sBl[b1]);
            }
#pragma unroll
            for (int mt = 0; mt < 4; mt++) {
                int r0 = buf * ABUF + (wm + mt * 16 + qr) * APAD + kk + qc;
                int r1 = r0 + 8 * APAD;
                unsigned ah[4], al[4];
                ah[0] = __float_as_uint(sAh[r0]);
                ah[1] = __float_as_uint(sAh[r1]);
                ah[2] = __float_as_uint(sAh[r0 + 4]);
                ah[3] = __float_as_uint(sAh[r1 + 4]);
                al[0] = __float_as_uint(sAl[r0]);
                al[1] = __float_as_uint(sAl[r1]);
                al[2] = __float_as_uint(sAl[r0 + 4]);
                al[3] = __float_as_uint(sAl[r1 + 4]);
#pragma unroll
                for (int nt = 0; nt < 4; nt++) {
                    mma8(acc[mt][nt], ah, bh[nt]);   // hi*hi
                    mma8(acc[mt][nt], ah, bl[nt]);   // hi*lo
                    mma8(acc[mt][nt], al, bh[nt]);   // lo*hi
                }
            }
        }

        if (s + 1 < NSTAGE) {
            STORE_S(buf ^ 1)
            __syncthreads();
        }
    }

    // epilogue: scale by dis[row], write g_y
    float* gy = (float*)g_y;
#pragma unroll
    for (int mt = 0; mt < 4; mt++) {
        int m0 = rowBase + wm + mt * 16 + qr;
        int m1 = m0 + 8;
        float s0 = (m0 < n) ? g_dis[m0] : 0.f;
        float s1 = (m1 < n) ? g_dis[m1] : 0.f;
#pragma unroll
        for (int nt = 0; nt < 4; nt++) {
            int n0 = colBase + wn + nt * 8 + qc * 2;
            if (m0 < n) {
                float2 v = make_float2(acc[mt][nt][0] * s0, acc[mt][nt][1] * s0);
                *(float2*)(gy + (size_t)m0 * DD + n0) = v;
            }
            if (m1 < n) {
                float2 v = make_float2(acc[mt][nt][2] * s1, acc[mt][nt][3] * s1);
                *(float2*)(gy + (size_t)m1 * DD + n0) = v;
            }
        }
    }
}

// ---------------- pull + epilogue: H[v] = elu(dis[v]*(y[v] + sum_nbr y[s]) + b) ----

__device__ __forceinline__ float elu1(float x) {
    return x > 0.f ? x : (expf(x) - 1.0f);
}

__global__ void __launch_bounds__(256)
k_pull(const float4* __restrict__ b, float4* __restrict__ H, int n) {
    const int warp = (blockIdx.x * blockDim.x + threadIdx.x) >> 5;
    const int lane = threadIdx.x & 31;
    if (warp >= n) return;
    const int node = warp;

    const float4* yrow = g_y + (size_t)node * ND4;
    float4 acc0 = yrow[lane];
    float4 acc1 = yrow[lane + 32];

    int j   = g_rowptr[node];
    int end = g_rowptr[node + 1];

    for (; j + 1 < end; j += 2) {
        int s0 = g_nbr[j];
        int s1 = g_nbr[j + 1];
        const float4* p0 = g_y + (size_t)s0 * ND4;
        const float4* p1 = g_y + (size_t)s1 * ND4;
        float4 u0 = p0[lane];
        float4 u1 = p0[lane + 32];
        float4 v0 = p1[lane];
        float4 v1 = p1[lane + 32];
        acc0.x += u0.x; acc0.y += u0.y; acc0.z += u0.z; acc0.w += u0.w;
        acc1.x += u1.x; acc1.y += u1.y; acc1.z += u1.z; acc1.w += u1.w;
        acc0.x += v0.x; acc0.y += v0.y; acc0.z += v0.z; acc0.w += v0.w;
        acc1.x += v1.x; acc1.y += v1.y; acc1.z += v1.z; acc1.w += v1.w;
    }
    if (j < end) {
        int s0 = g_nbr[j];
        const float4* p0 = g_y + (size_t)s0 * ND4;
        float4 u0 = p0[lane];
        float4 u1 = p0[lane + 32];
        acc0.x += u0.x; acc0.y += u0.y; acc0.z += u0.z; acc0.w += u0.w;
        acc1.x += u1.x; acc1.y += u1.y; acc1.z += u1.z; acc1.w += u1.w;
    }

    float s = g_dis[node];
    float4 b0 = b[lane];
    float4 b1 = b[lane + 32];
    float4 o0, o1;
    o0.x = elu1(fmaf(acc0.x, s, b0.x));
    o0.y = elu1(fmaf(acc0.y, s, b0.y));
    o0.z = elu1(fmaf(acc0.z, s, b0.z));
    o0.w = elu1(fmaf(acc0.w, s, b0.w));
    o1.x = elu1(fmaf(acc1.x, s, b1.x));
    o1.y = elu1(fmaf(acc1.y, s, b1.y));
    o1.z = elu1(fmaf(acc1.z, s, b1.z));
    o1.w = elu1(fmaf(acc1.w, s, b1.w));
    H[(size_t)node * ND4 + lane]      = o0;
    H[(size_t)node * ND4 + lane + 32] = o1;
}

// ---------------- launch ----------------

extern "C" void kernel_launch(void* const* d_in, const int* in_sizes, int n_in,
                              void* d_out, int out_size) {
    const float* x  = (const float*)d_in[0];
    const void*  ei = d_in[1];
    const float* W1 = (const float*)d_in[2];
    const float* b1 = (const float*)d_in[3];
    const float* W2 = (const float*)d_in[4];
    const float* b2 = (const float*)d_in[5];
    float4* out = (float4*)d_out;

    int n = in_sizes[0] / DD;        // 100000
    int e = in_sizes[1] / 2;         // 3200000

    void* p_h = nullptr;
    cudaGetSymbolAddress(&p_h, g_h);
    float4* hbuf = (float4*)p_h;

    const size_t smBytes = (size_t)SM_FLOATS * sizeof(float);   // 75776
    cudaFuncSetAttribute(k_gemm_tc, cudaFuncAttributeMaxDynamicSharedMemorySize,
                         (int)smBytes);

    // CSR build
    k_probe    <<<1, 512>>>((const int*)ei);
    k_deg_zero <<<(n + 255) / 256, 256>>>(n);
    k_deg_accum<<<(e + 255) / 256, 256>>>(ei, e);
    k_scan     <<<1, 1024>>>(n);
    k_dis      <<<(n + 255) / 256, 256>>>(n);
    k_fill     <<<(e + 255) / 256, 256>>>(ei, e);

    dim3 gGrid(DD / 128, (n + 127) / 128);
    int pGrid = (n + 7) / 8;

    // layer 1: x -> g_h
    k_gemm_tc<<<gGrid, 256, smBytes>>>(x, W1, n);
    k_pull   <<<pGrid, 256>>>((const float4*)b1, hbuf, n);

    // layer 2: g_h -> out
    k_gemm_tc<<<gGrid, 256, smBytes>>>((const float*)hbuf, W2, n);
    k_pull   <<<pGrid, 256>>>((const float4*)b2, out, n);
}

// round 6
// speedup vs baseline: 2.6001x; 1.1465x over previous
#include <cuda_runtime.h>
#include <math.h>

#define NN 100000
#define DD 256
#define ND4 (DD / 4)
#define EE 3200000
#define SCAN_BLKS 400

// Scratch (static device globals)
__device__ float  g_dis[NN];
__device__ int    g_deg[NN];
__device__ int    g_rowptr[NN + 1];
__device__ int    g_cursor[NN];
__device__ int    g_nbr[EE];
__device__ int    g_bsum[SCAN_BLKS];
__device__ int    g_boff[SCAN_BLKS];
__device__ float4 g_y[(size_t)NN * ND4];
__device__ float4 g_h[(size_t)NN * ND4];
__device__ int    g_is32;

// ---------------- dtype probe ----------------

__global__ void k_probe(const int* __restrict__ ei_raw) {
    __shared__ int any;
    if (threadIdx.x == 0) any = 0;
    __syncthreads();
    if (ei_raw[threadIdx.x * 2 + 1] != 0) atomicOr(&any, 1);
    __syncthreads();
    if (threadIdx.x == 0) g_is32 = any;
}

__device__ __forceinline__ int edge_id(const void* p, size_t idx) {
    return g_is32 ? ((const int*)p)[idx] : (int)((const long long*)p)[idx];
}

// ---------------- degree / CSR build ----------------

__global__ void k_deg_zero(int n) {
    int i = blockIdx.x * blockDim.x + threadIdx.x;
    if (i < n) g_deg[i] = 0;
}

__global__ void k_deg_accum(const void* __restrict__ ei, int e) {
    int i = blockIdx.x * blockDim.x + threadIdx.x;
    if (i < e) atomicAdd(&g_deg[edge_id(ei, (size_t)e + i)], 1);
}

// Phase 1: per-block sums of deg (256 nodes per block)
__global__ void k_scan_part(int n) {
    const int tid = threadIdx.x;
    int i = blockIdx.x * 256 + tid;
    int v = (i < n) ? g_deg[i] : 0;
#pragma unroll
    for (int off = 16; off > 0; off >>= 1)
        v += __shfl_down_sync(0xffffffffu, v, off);
    __shared__ int ws[8];
    if ((tid & 31) == 0) ws[tid >> 5] = v;
    __syncthreads();
    if (tid == 0) {
        int s = 0;
#pragma unroll
        for (int w = 0; w < 8; w++) s += ws[w];
        g_bsum[blockIdx.x] = s;
    }
}

// Phase 2: exclusive scan of SCAN_BLKS partials (single small block)
__global__ void k_scan_mid(int n) {
    __shared__ int sm[512];
    const int t = threadIdx.x;
    sm[t] = (t < SCAN_BLKS) ? g_bsum[t] : 0;
    __syncthreads();
    for (int off = 1; off < 512; off <<= 1) {
        int v = (t >= off) ? sm[t - off] : 0;
        __syncthreads();
        sm[t] += v;
        __syncthreads();
    }
    if (t < SCAN_BLKS) g_boff[t] = (t > 0) ? sm[t - 1] : 0;   // exclusive
    if (t == 511) g_rowptr[n] = sm[511];                       // total
}

// Phase 3: per-block inclusive shuffle-scan + offset -> rowptr/cursor
__global__ void k_scan_out(int n) {
    const int tid  = threadIdx.x;
    const int lane = tid & 31;
    const int wid  = tid >> 5;
    int i = blockIdx.x * 256 + tid;
    int v = (i < n) ? g_deg[i] : 0;

    int incl = v;
#pragma unroll
    for (int off = 1; off < 32; off <<= 1) {
        int u = __shfl_up_sync(0xffffffffu, incl, off);
        if (lane >= off) incl += u;
    }
    __shared__ int ws[8];
    if (lane == 31) ws[wid] = incl;
    __syncthreads();
    int warpoff = 0;
#pragma unroll
    for (int w = 0; w < 8; w++)
        if (w < wid) warpoff += ws[w];

    int excl = g_boff[blockIdx.x] + warpoff + incl - v;
    if (i < n) {
        g_rowptr[i] = excl;
        g_cursor[i] = excl;
    }
}

__global__ void k_dis(int n) {
    int i = blockIdx.x * blockDim.x + threadIdx.x;
    if (i < n) g_dis[i] = rsqrtf((float)(g_deg[i] + 1));
}

__global__ void k_fill(const void* __restrict__ ei, int e) {
    int i = blockIdx.x * blockDim.x + threadIdx.x;
    if (i >= e) return;
    int s = edge_id(ei, i);
    int d = edge_id(ei, (size_t)e + i);
    int pos = atomicAdd(&g_cursor[d], 1);
    g_nbr[pos] = s;
}

// ---------------- tf32 helpers ----------------

__device__ __forceinline__ unsigned f2tf(float x) {
    unsigned r;
    asm("cvt.rna.tf32.f32 %0, %1;" : "=r"(r) : "f"(x));
    return r;
}

__device__ __forceinline__ void mma8(float acc[4], const unsigned a[4], const unsigned b[2]) {
    asm volatile(
        "mma.sync.aligned.m16n8k8.row.col.f32.tf32.tf32.f32 "
        "{%0,%1,%2,%3},{%4,%5,%6,%7},{%8,%9},{%0,%1,%2,%3};"
        : "+f"(acc[0]), "+f"(acc[1]), "+f"(acc[2]), "+f"(acc[3])
        : "r"(a[0]), "r"(a[1]), "r"(a[2]), "r"(a[3]), "r"(b[0]), "r"(b[1]));
}

// ---------------- GEMM: Y = (A @ W) * dis[row]  (tensor core, tf32 3-term split) ----

#define APAD 20
#define BPAD 136
#define ABUF (128 * APAD)
#define BBUF (16 * BPAD)
#define SM_FLOATS (2 * ABUF * 2 + 2 * BBUF * 2)

__global__ void __launch_bounds__(256)
k_gemm_tc(const float* __restrict__ A, const float* __restrict__ W, int n) {
    extern __shared__ float sm[];
    float* sAh = sm;
    float* sAl = sAh + 2 * ABUF;
    float* sBh = sAl + 2 * ABUF;
    float* sBl = sBh + 2 * BBUF;

    const int tid  = threadIdx.x;
    const int lane = tid & 31;
    const int warp = tid >> 5;
    const int wm = (warp & 1) * 64;
    const int wn = (warp >> 1) * 32;
    const int qr = lane >> 2;
    const int qc = lane & 3;
    const int rowBase = blockIdx.y * 128;
    const int colBase = blockIdx.x * 128;

    const int ar  = tid >> 2;
    const int ak4 = (tid & 3) * 4;
    const int bkr = tid >> 5;
    const int bc4 = (tid & 31) * 4;

    float acc[4][4][4] = {};
    float4 aR[2], bR[2];

#define LOAD_G(kbase)                                                              \
    {                                                                              \
        _Pragma("unroll")                                                          \
        for (int i = 0; i < 2; i++) {                                              \
            int grow = rowBase + ar + i * 64;                                      \
            aR[i] = make_float4(0.f, 0.f, 0.f, 0.f);                               \
            if (grow < n)                                                          \
                aR[i] = *(const float4*)(A + (size_t)grow * DD + (kbase) + ak4);   \
            bR[i] = *(const float4*)(W + (size_t)((kbase) + bkr + i * 8) * DD      \
                                        + colBase + bc4);                          \
        }                                                                          \
    }

#define STORE_S(buf)                                                               \
    {                                                                              \
        _Pragma("unroll")                                                          \
        for (int i = 0; i < 2; i++) {                                              \
            int abase = (buf) * ABUF + (ar + i * 64) * APAD + ak4;                 \
            const float* av = (const float*)&aR[i];                                \
            _Pragma("unroll")                                                      \
            for (int j = 0; j < 4; j++) {                                          \
                unsigned h = f2tf(av[j]);                                          \
                float hf = __uint_as_float(h);                                     \
                sAh[abase + j] = hf;                                               \
                sAl[abase + j] = __uint_as_float(f2tf(av[j] - hf));                \
            }                                                                      \
            int bbase = (buf) * BBUF + (bkr + i * 8) * BPAD + bc4;                 \
            const float* bv = (const float*)&bR[i];                                \
            _Pragma("unroll")                                                      \
            for (int j = 0; j < 4; j++) {                                          \
                unsigned h = f2tf(bv[j]);                                          \
                float hf = __uint_as_float(h);                                     \
                sBh[bbase + j] = hf;                                               \
                sBl[bbase + j] = __uint_as_float(f2tf(bv[j] - hf));                \
            }                                                                      \
        }                                                                          \
    }

    LOAD_G(0)
    STORE_S(0)
    __syncthreads();

    const int NSTAGE = DD / 16;
    for (int s = 0; s < NSTAGE; s++) {
        int buf = s & 1;
        if (s + 1 < NSTAGE) LOAD_G((s + 1) * 16)

#pragma unroll
        for (int kk = 0; kk < 16; kk += 8) {
            unsigned bh[4][2], bl[4][2];
#pragma unroll
            for (int nt = 0; nt < 4; nt++) {
                int nn = wn + nt * 8 + qr;
                int b0 = buf * BBUF + (kk + qc) * BPAD + nn;
                int b1 = buf * BBUF + (kk + qc + 4) * BPAD + nn;
                bh[nt][0] = __float_as_uint(sBh[b0]);
                bh[nt][1] = __float_as_uint(sBh[b1]);
                bl[nt][0] = __float_as_uint(sBl[b0]);
                bl[nt][1] = __float_as_uint(sBl[b1]);
            }
#pragma unroll
            for (int mt = 0; mt < 4; mt++) {
                int r0 = buf * ABUF + (wm + mt * 16 + qr) * APAD + kk + qc;
                int r1 = r0 + 8 * APAD;
                unsigned ah[4], al[4];
                ah[0] = __float_as_uint(sAh[r0]);
                ah[1] = __float_as_uint(sAh[r1]);
                ah[2] = __float_as_uint(sAh[r0 + 4]);
                ah[3] = __float_as_uint(sAh[r1 + 4]);
                al[0] = __float_as_uint(sAl[r0]);
                al[1] = __float_as_uint(sAl[r1]);
                al[2] = __float_as_uint(sAl[r0 + 4]);
                al[3] = __float_as_uint(sAl[r1 + 4]);
#pragma unroll
                for (int nt = 0; nt < 4; nt++) {
                    mma8(acc[mt][nt], ah, bh[nt]);
                    mma8(acc[mt][nt], ah, bl[nt]);
                    mma8(acc[mt][nt], al, bh[nt]);
                }
            }
        }

        if (s + 1 < NSTAGE) {
            STORE_S(buf ^ 1)
            __syncthreads();
        }
    }

    float* gy = (float*)g_y;
#pragma unroll
    for (int mt = 0; mt < 4; mt++) {
        int m0 = rowBase + wm + mt * 16 + qr;
        int m1 = m0 + 8;
        float s0 = (m0 < n) ? g_dis[m0] : 0.f;
        float s1 = (m1 < n) ? g_dis[m1] : 0.f;
#pragma unroll
        for (int nt = 0; nt < 4; nt++) {
            int n0 = colBase + wn + nt * 8 + qc * 2;
            if (m0 < n) {
                float2 v = make_float2(acc[mt][nt][0] * s0, acc[mt][nt][1] * s0);
                *(float2*)(gy + (size_t)m0 * DD + n0) = v;
            }
            if (m1 < n) {
                float2 v = make_float2(acc[mt][nt][2] * s1, acc[mt][nt][3] * s1);
                *(float2*)(gy + (size_t)m1 * DD + n0) = v;
            }
        }
    }
}

// ---------------- pull + epilogue ----------------

__device__ __forceinline__ float elu1(float x) {
    return x > 0.f ? x : (expf(x) - 1.0f);
}

__global__ void __launch_bounds__(256)
k_pull(const float4* __restrict__ b, float4* __restrict__ H, int n) {
    const int warp = (blockIdx.x * blockDim.x + threadIdx.x) >> 5;
    const int lane = threadIdx.x & 31;
    if (warp >= n) return;
    const int node = warp;

    const float4* yrow = g_y + (size_t)node * ND4;
    float4 acc0 = yrow[lane];
    float4 acc1 = yrow[lane + 32];

    int j   = g_rowptr[node];
    int end = g_rowptr[node + 1];

    for (; j + 1 < end; j += 2) {
        int s0 = g_nbr[j];
        int s1 = g_nbr[j + 1];
        const float4* p0 = g_y + (size_t)s0 * ND4;
        const float4* p1 = g_y + (size_t)s1 * ND4;
        float4 u0 = p0[lane];
        float4 u1 = p0[lane + 32];
        float4 v0 = p1[lane];
        float4 v1 = p1[lane + 32];
        acc0.x += u0.x; acc0.y += u0.y; acc0.z += u0.z; acc0.w += u0.w;
        acc1.x += u1.x; acc1.y += u1.y; acc1.z += u1.z; acc1.w += u1.w;
        acc0.x += v0.x; acc0.y += v0.y; acc0.z += v0.z; acc0.w += v0.w;
        acc1.x += v1.x; acc1.y += v1.y; acc1.z += v1.z; acc1.w += v1.w;
    }
    if (j < end) {
        int s0 = g_nbr[j];
        const float4* p0 = g_y + (size_t)s0 * ND4;
        float4 u0 = p0[lane];
        float4 u1 = p0[lane + 32];
        acc0.x += u0.x; acc0.y += u0.y; acc0.z += u0.z; acc0.w += u0.w;
        acc1.x += u1.x; acc1.y += u1.y; acc1.z += u1.z; acc1.w += u1.w;
    }

    float s = g_dis[node];
    float4 b0 = b[lane];
    float4 b1 = b[lane + 32];
    float4 o0, o1;
    o0.x = elu1(fmaf(acc0.x, s, b0.x));
    o0.y = elu1(fmaf(acc0.y, s, b0.y));
    o0.z = elu1(fmaf(acc0.z, s, b0.z));
    o0.w = elu1(fmaf(acc0.w, s, b0.w));
    o1.x = elu1(fmaf(acc1.x, s, b1.x));
    o1.y = elu1(fmaf(acc1.y, s, b1.y));
    o1.z = elu1(fmaf(acc1.z, s, b1.z));
    o1.w = elu1(fmaf(acc1.w, s, b1.w));
    H[(size_t)node * ND4 + lane]      = o0;
    H[(size_t)node * ND4 + lane + 32] = o1;
}

// ---------------- launch ----------------

extern "C" void kernel_launch(void* const* d_in, const int* in_sizes, int n_in,
                              void* d_out, int out_size) {
    const float* x  = (const float*)d_in[0];
    const void*  ei = d_in[1];
    const float* W1 = (const float*)d_in[2];
    const float* b1 = (const float*)d_in[3];
    const float* W2 = (const float*)d_in[4];
    const float* b2 = (const float*)d_in[5];
    float4* out = (float4*)d_out;

    int n = in_sizes[0] / DD;        // 100000
    int e = in_sizes[1] / 2;         // 3200000

    void* p_h = nullptr;
    cudaGetSymbolAddress(&p_h, g_h);
    float4* hbuf = (float4*)p_h;

    const size_t smBytes = (size_t)SM_FLOATS * sizeof(float);
    cudaFuncSetAttribute(k_gemm_tc, cudaFuncAttributeMaxDynamicSharedMemorySize,
                         (int)smBytes);

    // CSR build
    k_probe    <<<1, 512>>>((const int*)ei);
    k_deg_zero <<<(n + 255) / 256, 256>>>(n);
    k_deg_accum<<<(e + 255) / 256, 256>>>(ei, e);
    k_scan_part<<<SCAN_BLKS, 256>>>(n);
    k_scan_mid <<<1, 512>>>(n);
    k_scan_out <<<SCAN_BLKS, 256>>>(n);
    k_dis      <<<(n + 255) / 256, 256>>>(n);
    k_fill     <<<(e + 255) / 256, 256>>>(ei, e);

    dim3 gGrid(DD / 128, (n + 127) / 128);
    int pGrid = (n + 7) / 8;

    // layer 1: x -> g_h
    k_gemm_tc<<<gGrid, 256, smBytes>>>(x, W1, n);
    k_pull   <<<pGrid, 256>>>((const float4*)b1, hbuf, n);

    // layer 2: g_h -> out
    k_gemm_tc<<<gGrid, 256, smBytes>>>((const float*)hbuf, W2, n);
    k_pull   <<<pGrid, 256>>>((const float4*)b2, out, n);
}